// round 1
// baseline (speedup 1.0000x reference)
#include <cuda_runtime.h>
#include <math.h>

static constexpr int NG  = 512;
static constexpr int IMW = 256;
static constexpr int IMH = 256;
static constexpr float TANFOVX = 0.5f;
static constexpr float TANFOVY = 0.5f;
static constexpr float FXc = IMW / (2.0f * TANFOVX);
static constexpr float FYc = IMH / (2.0f * TANFOVY);

// Sorted per-gaussian params (scratch; allocation-free via __device__ globals)
__device__ float g_mx[NG], g_my[NG], g_A[NG], g_B[NG], g_C[NG], g_op[NG],
                 g_cr[NG], g_cg[NG], g_cb[NG], g_z[NG], g_r2[NG];

__global__ void preprocess_kernel(const float* __restrict__ means3D,
                                  const float* __restrict__ opac,
                                  const float* __restrict__ cols,
                                  const float* __restrict__ scales,
                                  const float* __restrict__ rots,
                                  const float* __restrict__ vm,
                                  const float* __restrict__ pm,
                                  float* __restrict__ out_radii)
{
    __shared__ float s_tz[NG];
    int i = threadIdx.x;

    float m0 = means3D[3*i + 0], m1 = means3D[3*i + 1], m2 = means3D[3*i + 2];

    // quaternion -> rotation (normalized)
    float qr = rots[4*i+0], qx = rots[4*i+1], qy = rots[4*i+2], qz = rots[4*i+3];
    float qn = rsqrtf(qr*qr + qx*qx + qy*qy + qz*qz);
    qr *= qn; qx *= qn; qy *= qn; qz *= qn;
    float R[3][3] = {
        {1.f - 2.f*(qy*qy + qz*qz), 2.f*(qx*qy - qr*qz),       2.f*(qx*qz + qr*qy)},
        {2.f*(qx*qy + qr*qz),       1.f - 2.f*(qx*qx + qz*qz), 2.f*(qy*qz - qr*qx)},
        {2.f*(qx*qz - qr*qy),       2.f*(qy*qz + qr*qx),       1.f - 2.f*(qx*qx + qy*qy)}};

    float sc[3] = {scales[3*i+0], scales[3*i+1], scales[3*i+2]};
    float M[3][3];
    #pragma unroll
    for (int r = 0; r < 3; r++)
        #pragma unroll
        for (int c = 0; c < 3; c++)
            M[r][c] = R[r][c] * sc[c];

    // Sigma = M M^T
    float Sg[3][3];
    #pragma unroll
    for (int a = 0; a < 3; a++)
        #pragma unroll
        for (int b = 0; b < 3; b++)
            Sg[a][b] = M[a][0]*M[b][0] + M[a][1]*M[b][1] + M[a][2]*M[b][2];

    // view transform: t = [m,1] @ V
    float t0 = m0*vm[0] + m1*vm[4] + m2*vm[8]  + vm[12];
    float t1 = m0*vm[1] + m1*vm[5] + m2*vm[9]  + vm[13];
    float tz = m0*vm[2] + m1*vm[6] + m2*vm[10] + vm[14];
    float tzc = fmaxf(tz, 0.0001f);
    const float limx = 1.3f * TANFOVX, limy = 1.3f * TANFOVY;
    float txc = fminf(fmaxf(t0 / tzc, -limx), limx) * tzc;
    float tyc = fminf(fmaxf(t1 / tzc, -limy), limy) * tzc;

    float J[2][3] = {
        {FXc / tzc, 0.f,        -FXc * txc / (tzc * tzc)},
        {0.f,       FYc / tzc,  -FYc * tyc / (tzc * tzc)}};

    // T2 = J @ Wc, Wc[j][k] = V[k][j] = vm[k*4+j]
    float T2[2][3];
    #pragma unroll
    for (int a = 0; a < 2; a++)
        #pragma unroll
        for (int k = 0; k < 3; k++)
            T2[a][k] = J[a][0]*vm[k*4+0] + J[a][1]*vm[k*4+1] + J[a][2]*vm[k*4+2];

    // cov2d = T2 Sigma T2^T
    float U[2][3];
    #pragma unroll
    for (int a = 0; a < 2; a++)
        #pragma unroll
        for (int k = 0; k < 3; k++)
            U[a][k] = T2[a][0]*Sg[0][k] + T2[a][1]*Sg[1][k] + T2[a][2]*Sg[2][k];

    float c00 = U[0][0]*T2[0][0] + U[0][1]*T2[0][1] + U[0][2]*T2[0][2] + 0.3f;
    float c01 = U[0][0]*T2[1][0] + U[0][1]*T2[1][1] + U[0][2]*T2[1][2];
    float c11 = U[1][0]*T2[1][0] + U[1][1]*T2[1][1] + U[1][2]*T2[1][2] + 0.3f;

    float det = c00*c11 - c01*c01;
    float det_inv = 1.0f / (det != 0.f ? det : 1.f);
    float Ai = c11 * det_inv;
    float Bi = -c01 * det_inv;
    float Ci = c00 * det_inv;
    float mid = 0.5f * (c00 + c11);
    float lam = mid + sqrtf(fmaxf(mid*mid - det, 0.1f));
    bool vis = (det > 0.f) && (tz > 0.2f);
    out_radii[i] = vis ? ceilf(3.0f * sqrtf(lam)) : 0.0f;

    // projection
    float p0 = m0*pm[0] + m1*pm[4] + m2*pm[8]  + pm[12];
    float p1 = m0*pm[1] + m1*pm[5] + m2*pm[9]  + pm[13];
    float p3 = m0*pm[3] + m1*pm[7] + m2*pm[11] + pm[15];
    float pw = 1.0f / (p3 + 1e-7f);
    float mx = ((p0*pw + 1.0f) * IMW - 1.0f) * 0.5f;
    float my = ((p1*pw + 1.0f) * IMH - 1.0f) * 0.5f;

    float op = opac[i];
    float r2;
    if (!vis || !(op * 255.f > 1.f)) {
        op = 0.f; r2 = -1.f;   // never contributes (exact: alpha==0 in reference)
    } else {
        // alpha >= 1/255 requires |d|^2 <= 2*lam*ln(255*op)  (lam >= true lambda_max)
        r2 = 2.0f * lam * logf(255.f * op);
    }

    // stable rank sort by tz (ascending)
    s_tz[i] = tz;
    __syncthreads();
    int rank = 0;
    #pragma unroll 8
    for (int j = 0; j < NG; j++) {
        float v = s_tz[j];
        rank += (v < tz) || (v == tz && j < i);
    }

    g_mx[rank] = mx;  g_my[rank] = my;
    g_A[rank]  = Ai;  g_B[rank]  = Bi;  g_C[rank] = Ci;
    g_op[rank] = op;  g_z[rank]  = tz;  g_r2[rank] = r2;
    g_cr[rank] = cols[3*i+0];
    g_cg[rank] = cols[3*i+1];
    g_cb[rank] = cols[3*i+2];
}

__global__ void __launch_bounds__(256) raster_kernel(const float* __restrict__ bg,
                                                     float* __restrict__ out)
{
    __shared__ float s_mx[NG], s_my[NG], s_A[NG], s_B[NG], s_C[NG],
                     s_op[NG], s_cr[NG], s_cg[NG], s_cb[NG], s_z[NG];
    __shared__ int s_wsum[8], s_woff[8], s_total;

    int tid = threadIdx.x;
    int tilex = blockIdx.x & 15, tiley = blockIdx.x >> 4;
    float x0 = (float)(tilex * 16), y0 = (float)(tiley * 16);
    float x1 = x0 + 15.f, y1 = y0 + 15.f;

    // order-preserving compaction of gaussians overlapping this tile
    int count = 0;
    #pragma unroll
    for (int c = 0; c < NG / 256; c++) {
        int g = c * 256 + tid;
        float mx = g_mx[g], my = g_my[g], r2 = g_r2[g];
        float cx = fminf(fmaxf(mx, x0), x1);
        float cy = fminf(fmaxf(my, y0), y1);
        float ddx = mx - cx, ddy = my - cy;
        bool keep = (r2 >= 0.f) && (ddx*ddx + ddy*ddy <= r2);

        unsigned bal = __ballot_sync(0xffffffffu, keep);
        int lane = tid & 31, warp = tid >> 5;
        if (lane == 0) s_wsum[warp] = __popc(bal);
        __syncthreads();
        if (tid == 0) {
            int acc = 0;
            #pragma unroll
            for (int w = 0; w < 8; w++) { s_woff[w] = acc; acc += s_wsum[w]; }
            s_total = acc;
        }
        __syncthreads();
        if (keep) {
            int pos = count + s_woff[warp] + __popc(bal & ((1u << lane) - 1u));
            s_mx[pos] = mx;      s_my[pos] = my;
            s_A[pos]  = g_A[g];  s_B[pos]  = g_B[g];  s_C[pos] = g_C[g];
            s_op[pos] = g_op[g]; s_z[pos]  = g_z[g];
            s_cr[pos] = g_cr[g]; s_cg[pos] = g_cg[g]; s_cb[pos] = g_cb[g];
        }
        count += s_total;
        __syncthreads();
    }

    float px = x0 + (float)(tid & 15);
    float py = y0 + (float)(tid >> 4);

    float T = 1.f, cr = 0.f, cg = 0.f, cb = 0.f, dep = 0.f;
    for (int k = 0; k < count; k++) {
        float dx = s_mx[k] - px;
        float dy = s_my[k] - py;
        float power = -0.5f * (s_A[k]*dx*dx + s_C[k]*dy*dy) - s_B[k]*dx*dy;
        if (power > 0.f) continue;
        float alpha = fminf(0.99f, s_op[k] * __expf(power));
        if (alpha < (1.f / 255.f)) continue;
        float w = alpha * T;
        cr += w * s_cr[k];
        cg += w * s_cg[k];
        cb += w * s_cb[k];
        dep += w * s_z[k];
        T *= (1.f - alpha);
    }

    int pidx = ((tiley * 16) + (tid >> 4)) * IMW + (tilex * 16) + (tid & 15);
    const int HW = IMH * IMW;
    out[0*HW + pidx] = cr + T * bg[0];
    out[1*HW + pidx] = cg + T * bg[1];
    out[2*HW + pidx] = cb + T * bg[2];
    out[3*HW + pidx] = dep;     // depth
    out[4*HW + pidx] = T;       // Tfinal
}

extern "C" void kernel_launch(void* const* d_in, const int* in_sizes, int n_in,
                              void* d_out, int out_size)
{
    const float* means3D = (const float*)d_in[0];
    const float* opac    = (const float*)d_in[1];
    const float* cols    = (const float*)d_in[2];
    const float* scales  = (const float*)d_in[3];
    const float* rots    = (const float*)d_in[4];
    const float* bg      = (const float*)d_in[5];
    const float* vm      = (const float*)d_in[6];
    const float* pm      = (const float*)d_in[7];
    float* out = (float*)d_out;

    // output layout: color(3*H*W), depth(H*W), Tfinal(H*W), radii(N) as float
    preprocess_kernel<<<1, NG>>>(means3D, opac, cols, scales, rots, vm, pm,
                                 out + 5 * IMH * IMW);
    raster_kernel<<<256, 256>>>(bg, out);
}

// round 2
// speedup vs baseline: 2.0991x; 2.0991x over previous
#include <cuda_runtime.h>
#include <math.h>

static constexpr int NG  = 512;
static constexpr int IMW = 256;
static constexpr int IMH = 256;
static constexpr float TANFOVX = 0.5f;
static constexpr float TANFOVY = 0.5f;
static constexpr float FXc = IMW / (2.0f * TANFOVX);
static constexpr float FYc = IMH / (2.0f * TANFOVY);

__global__ void __launch_bounds__(256) fused_raster_kernel(
    const float* __restrict__ means3D,
    const float* __restrict__ opac,
    const float* __restrict__ cols,
    const float* __restrict__ scales,
    const float* __restrict__ rots,
    const float* __restrict__ bg,
    const float* __restrict__ vm_g,
    const float* __restrict__ pm_g,
    float* __restrict__ out)
{
    // set A: tile-compacted (original order); set B: depth-sorted
    __shared__ float a_mx[NG], a_my[NG], a_A[NG], a_B[NG], a_C[NG],
                     a_op[NG], a_cr[NG], a_cg[NG], a_cb[NG], a_z[NG];
    __shared__ float b_mx[NG], b_my[NG], b_A[NG], b_B[NG], b_C[NG],
                     b_op[NG], b_cr[NG], b_cg[NG], b_cb[NG], b_z[NG];
    __shared__ float vm[16], pm[16], s_bg[3];
    __shared__ int   s_wsum[8], s_woff[8], s_total;

    const int tid = threadIdx.x;
    if (tid < 16) { vm[tid] = vm_g[tid]; pm[tid] = pm_g[tid]; }
    if (tid < 3)  { s_bg[tid] = bg[tid]; }
    __syncthreads();

    const int tilex = blockIdx.x & 15, tiley = blockIdx.x >> 4;
    const float x0 = (float)(tilex * 16), y0 = (float)(tiley * 16);
    const float x1 = x0 + 15.f, y1 = y0 + 15.f;

    // ---- fused preprocess + order-preserving tile compaction ----
    int count = 0;
    #pragma unroll
    for (int c = 0; c < NG / 256; c++) {
        const int g = c * 256 + tid;

        float m0 = means3D[3*g+0], m1 = means3D[3*g+1], m2 = means3D[3*g+2];

        float qr = rots[4*g+0], qx = rots[4*g+1], qy = rots[4*g+2], qz = rots[4*g+3];
        float qn = rsqrtf(qr*qr + qx*qx + qy*qy + qz*qz);
        qr *= qn; qx *= qn; qy *= qn; qz *= qn;
        float R[3][3] = {
            {1.f - 2.f*(qy*qy + qz*qz), 2.f*(qx*qy - qr*qz),       2.f*(qx*qz + qr*qy)},
            {2.f*(qx*qy + qr*qz),       1.f - 2.f*(qx*qx + qz*qz), 2.f*(qy*qz - qr*qx)},
            {2.f*(qx*qz - qr*qy),       2.f*(qy*qz + qr*qx),       1.f - 2.f*(qx*qx + qy*qy)}};

        float sc0 = scales[3*g+0], sc1 = scales[3*g+1], sc2 = scales[3*g+2];
        float M[3][3];
        #pragma unroll
        for (int r = 0; r < 3; r++) {
            M[r][0] = R[r][0] * sc0;
            M[r][1] = R[r][1] * sc1;
            M[r][2] = R[r][2] * sc2;
        }
        float Sg[3][3];
        #pragma unroll
        for (int a = 0; a < 3; a++)
            #pragma unroll
            for (int b = 0; b < 3; b++)
                Sg[a][b] = M[a][0]*M[b][0] + M[a][1]*M[b][1] + M[a][2]*M[b][2];

        float t0 = m0*vm[0] + m1*vm[4] + m2*vm[8]  + vm[12];
        float t1 = m0*vm[1] + m1*vm[5] + m2*vm[9]  + vm[13];
        float tz = m0*vm[2] + m1*vm[6] + m2*vm[10] + vm[14];
        float tzc = fmaxf(tz, 0.0001f);
        const float limx = 1.3f * TANFOVX, limy = 1.3f * TANFOVY;
        float txc = fminf(fmaxf(t0 / tzc, -limx), limx) * tzc;
        float tyc = fminf(fmaxf(t1 / tzc, -limy), limy) * tzc;

        float J[2][3] = {
            {FXc / tzc, 0.f,       -FXc * txc / (tzc * tzc)},
            {0.f,       FYc / tzc, -FYc * tyc / (tzc * tzc)}};

        float T2[2][3];
        #pragma unroll
        for (int a = 0; a < 2; a++)
            #pragma unroll
            for (int k = 0; k < 3; k++)
                T2[a][k] = J[a][0]*vm[k*4+0] + J[a][1]*vm[k*4+1] + J[a][2]*vm[k*4+2];

        float U[2][3];
        #pragma unroll
        for (int a = 0; a < 2; a++)
            #pragma unroll
            for (int k = 0; k < 3; k++)
                U[a][k] = T2[a][0]*Sg[0][k] + T2[a][1]*Sg[1][k] + T2[a][2]*Sg[2][k];

        float c00 = U[0][0]*T2[0][0] + U[0][1]*T2[0][1] + U[0][2]*T2[0][2] + 0.3f;
        float c01 = U[0][0]*T2[1][0] + U[0][1]*T2[1][1] + U[0][2]*T2[1][2];
        float c11 = U[1][0]*T2[1][0] + U[1][1]*T2[1][1] + U[1][2]*T2[1][2] + 0.3f;

        float det = c00*c11 - c01*c01;
        float det_inv = 1.0f / (det != 0.f ? det : 1.f);
        float Ai = c11 * det_inv;
        float Bi = -c01 * det_inv;
        float Ci = c00 * det_inv;
        float mid = 0.5f * (c00 + c11);
        float lam = mid + sqrtf(fmaxf(mid*mid - det, 0.1f));
        bool vis = (det > 0.f) && (tz > 0.2f);

        if (blockIdx.x == 0)
            out[5 * IMH * IMW + g] = vis ? ceilf(3.0f * sqrtf(lam)) : 0.0f;

        float p0 = m0*pm[0] + m1*pm[4] + m2*pm[8]  + pm[12];
        float p1 = m0*pm[1] + m1*pm[5] + m2*pm[9]  + pm[13];
        float p3 = m0*pm[3] + m1*pm[7] + m2*pm[11] + pm[15];
        float pw = 1.0f / (p3 + 1e-7f);
        float mx = ((p0*pw + 1.0f) * IMW - 1.0f) * 0.5f;
        float my = ((p1*pw + 1.0f) * IMH - 1.0f) * 0.5f;

        float op = opac[g];
        float r2 = -1.f;
        if (vis && (op * 255.f > 1.f)) {
            // alpha >= 1/255 requires |d|^2 <= 2*lam*ln(255*op) (lam >= lambda_max)
            r2 = 2.0f * lam * logf(255.f * op);
        } else {
            op = 0.f;
        }

        // tile overlap test (conservative-exact vs the 1/255 alpha cutoff)
        float cx = fminf(fmaxf(mx, x0), x1);
        float cy = fminf(fmaxf(my, y0), y1);
        float ddx = mx - cx, ddy = my - cy;
        bool keep = (r2 >= 0.f) && (ddx*ddx + ddy*ddy <= r2);

        unsigned bal = __ballot_sync(0xffffffffu, keep);
        int lane = tid & 31, warp = tid >> 5;
        if (lane == 0) s_wsum[warp] = __popc(bal);
        __syncthreads();
        if (tid == 0) {
            int acc = 0;
            #pragma unroll
            for (int w = 0; w < 8; w++) { s_woff[w] = acc; acc += s_wsum[w]; }
            s_total = acc;
        }
        __syncthreads();
        if (keep) {
            int pos = count + s_woff[warp] + __popc(bal & ((1u << lane) - 1u));
            a_mx[pos] = mx;  a_my[pos] = my;
            a_A[pos]  = Ai;  a_B[pos]  = Bi;  a_C[pos] = Ci;
            a_op[pos] = op;  a_z[pos]  = tz;
            a_cr[pos] = cols[3*g+0];
            a_cg[pos] = cols[3*g+1];
            a_cb[pos] = cols[3*g+2];
        }
        count += s_total;
        __syncthreads();
    }

    // ---- per-tile stable rank sort by depth (compaction preserved index order) ----
    for (int k = tid; k < count; k += 256) {
        float zk = a_z[k];
        int rank = 0;
        for (int j = 0; j < count; j++) {
            float zj = a_z[j];
            rank += (zj < zk) || (zj == zk && j < k);
        }
        b_mx[rank] = a_mx[k];  b_my[rank] = a_my[k];
        b_A[rank]  = a_A[k];   b_B[rank]  = a_B[k];  b_C[rank] = a_C[k];
        b_op[rank] = a_op[k];  b_z[rank]  = a_z[k];
        b_cr[rank] = a_cr[k];  b_cg[rank] = a_cg[k]; b_cb[rank] = a_cb[k];
    }
    __syncthreads();

    // ---- per-pixel front-to-back compositing ----
    const float px = x0 + (float)(tid & 15);
    const float py = y0 + (float)(tid >> 4);

    float T = 1.f, cr = 0.f, cg = 0.f, cb = 0.f, dep = 0.f;
    for (int k = 0; k < count; k++) {
        float dx = b_mx[k] - px;
        float dy = b_my[k] - py;
        float power = -0.5f * (b_A[k]*dx*dx + b_C[k]*dy*dy) - b_B[k]*dx*dy;
        if (power > 0.f) continue;
        float alpha = fminf(0.99f, b_op[k] * __expf(power));
        if (alpha < (1.f / 255.f)) continue;
        float w = alpha * T;
        cr  += w * b_cr[k];
        cg  += w * b_cg[k];
        cb  += w * b_cb[k];
        dep += w * b_z[k];
        T *= (1.f - alpha);
    }

    const int pidx = ((tiley * 16) + (tid >> 4)) * IMW + (tilex * 16) + (tid & 15);
    const int HW = IMH * IMW;
    out[0*HW + pidx] = cr + T * s_bg[0];
    out[1*HW + pidx] = cg + T * s_bg[1];
    out[2*HW + pidx] = cb + T * s_bg[2];
    out[3*HW + pidx] = dep;   // depth
    out[4*HW + pidx] = T;     // Tfinal
}

extern "C" void kernel_launch(void* const* d_in, const int* in_sizes, int n_in,
                              void* d_out, int out_size)
{
    const float* means3D = (const float*)d_in[0];
    const float* opac    = (const float*)d_in[1];
    const float* cols    = (const float*)d_in[2];
    const float* scales  = (const float*)d_in[3];
    const float* rots    = (const float*)d_in[4];
    const float* bg      = (const float*)d_in[5];
    const float* vm      = (const float*)d_in[6];
    const float* pm      = (const float*)d_in[7];
    float* out = (float*)d_out;

    // output layout: color(3*H*W), depth(H*W), Tfinal(H*W), radii(N)
    fused_raster_kernel<<<256, 256>>>(means3D, opac, cols, scales, rots,
                                      bg, vm, pm, out);
}